// round 3
// baseline (speedup 1.0000x reference)
#include <cuda_runtime.h>

// NT-Xent loss. inp: (C=8, V=2, B=4096, D=512) fp32.
// Warp-per-b: lane owns D-slice (float2 per chunk, 8 chunks of 64 floats).
// G[i][k] (8 anchors x 16 cols) in registers via packed f32x2 FMA (k-paired).
// Odd-row sumsq fused (even norms come from Gram diagonal G[i][2i]).
// Folded butterfly -> lane L owns G[L>>2][4*(L&3)+m]; in-warp LSE epilogue.

static constexpr int      kB   = 4096;
static constexpr unsigned FULL = 0xffffffffu;

__device__ float    g_partials[kB];
__device__ unsigned g_ticket;   // zero-init; reset by last CTA every launch

__device__ __forceinline__ unsigned long long pack2(float lo, float hi) {
    unsigned long long r;
    asm("mov.b64 %0, {%1, %2};" : "=l"(r) : "f"(lo), "f"(hi));
    return r;
}
__device__ __forceinline__ void unpack2(unsigned long long v, float& lo, float& hi) {
    asm("mov.b64 {%0, %1}, %2;" : "=f"(lo), "=f"(hi) : "l"(v));
}
__device__ __forceinline__ void ffma2(unsigned long long& acc,
                                      unsigned long long a, unsigned long long b) {
    asm("fma.rn.f32x2 %0, %1, %2, %0;" : "+l"(acc) : "l"(a), "l"(b));
}

__global__ void __launch_bounds__(128)
ntxent_warp(const float* __restrict__ inp, float* __restrict__ out)
{
    __shared__ float    snorm[4][16];
    __shared__ float    sred[4];
    __shared__ unsigned sFlag;

    const int tid  = threadIdx.x;
    const int w    = tid >> 5;
    const int lane = tid & 31;
    const int b    = blockIdx.x * 4 + w;

    // float2 view: row stride = 4096*512/2 = 1048576; b offset = 256; lane offset = lane
    const float2* base = reinterpret_cast<const float2*>(inp) + (size_t)b * 256 + lane;

    unsigned long long acc2[64];   // acc2[i*8+k2] = (G[i][2k2], G[i][2k2+1]) d-partials
    unsigned long long ss2[8];     // odd-row sumsq, d-paired
    #pragma unroll
    for (int q = 0; q < 64; q++) acc2[q] = 0ull;
    #pragma unroll
    for (int q = 0; q < 8; q++)  ss2[q] = 0ull;

    #pragma unroll
    for (int c = 0; c < 8; c++) {
        float2 xb[16];
        #pragma unroll
        for (int r = 0; r < 16; r++)
            xb[r] = __ldcs(base + (size_t)r * 1048576 + c * 32);

        // odd-row sum-of-squares (natural register pair: no packing cost)
        #pragma unroll
        for (int p = 0; p < 8; p++) {
            unsigned long long o = pack2(xb[2 * p + 1].x, xb[2 * p + 1].y);
            ffma2(ss2[p], o, o);
        }

        #pragma unroll
        for (int d = 0; d < 2; d++) {
            unsigned long long xp[8];
            #pragma unroll
            for (int k2 = 0; k2 < 8; k2++)
                xp[k2] = pack2(d ? xb[2 * k2].y     : xb[2 * k2].x,
                               d ? xb[2 * k2 + 1].y : xb[2 * k2 + 1].x);
            #pragma unroll
            for (int i = 0; i < 8; i++) {
                const float av = d ? xb[2 * i].y : xb[2 * i].x;   // anchor = row 2i
                const unsigned long long ad = pack2(av, av);
                #pragma unroll
                for (int k2 = 0; k2 < 8; k2++)
                    ffma2(acc2[i * 8 + k2], ad, xp[k2]);
            }
        }
    }

    // ---- unpack to 128 scalars ----
    float a[128];
    #pragma unroll
    for (int i = 0; i < 8; i++)
        #pragma unroll
        for (int k2 = 0; k2 < 8; k2++)
            unpack2(acc2[i * 8 + k2], a[i * 16 + 2 * k2], a[i * 16 + 2 * k2 + 1]);

    // ---- folded butterfly: 128 lane-partials -> lane L owns G[(L<<2)+m], m=0..3 ----
    #pragma unroll
    for (int s = 0; s < 5; s++) {
        const int  off = 16 >> s;
        const int  n   = 64 >> s;
        const bool hi  = (lane & off) != 0;
        #pragma unroll
        for (int m = 0; m < n; m++) {
            const float mine = hi ? a[m + n] : a[m];
            const float send = hi ? a[m]     : a[m + n];
            a[m] = mine + __shfl_xor_sync(FULL, send, off);
        }
    }
    // now: i = lane>>2, cols k = 4*(lane&3)+m, G[i][k] = a[m]

    // ---- odd-row sumsq reduce: lane L -> ||row 2*(L>>2)+1||^2 ----
    float sv[8];
    #pragma unroll
    for (int p = 0; p < 8; p++) { float lo, hi2; unpack2(ss2[p], lo, hi2); sv[p] = lo + hi2; }
    #pragma unroll
    for (int s = 0; s < 3; s++) {
        const int  off = 16 >> s;
        const int  n   = 4 >> s;
        const bool hi  = (lane & off) != 0;
        #pragma unroll
        for (int m = 0; m < n; m++) {
            const float mine = hi ? sv[m + n] : sv[m];
            const float send = hi ? sv[m]     : sv[m + n];
            sv[m] = mine + __shfl_xor_sync(FULL, send, off);
        }
    }
    float ssodd = sv[0];
    ssodd += __shfl_xor_sync(FULL, ssodd, 2);
    ssodd += __shfl_xor_sync(FULL, ssodd, 1);

    // ---- stage the 16 squared norms in per-warp smem ----
    const int i = lane >> 2;
    if ((lane & 3) == 0) snorm[w][2 * i + 1] = ssodd;           // odd rows
    #pragma unroll
    for (int m = 0; m < 4; m++) {                                // even rows: Gram diag
        const int j = 4 * lane + m;                              // j = i*16 + k
        if ((j & 15) == 2 * (j >> 4)) snorm[w][j & 15] = a[m];
    }
    __syncwarp();

    // ---- LSE epilogue, fully in-warp ----
    const float inva  = 1.0f / fmaxf(sqrtf(snorm[w][2 * i]), 1e-12f);
    const int   kbase = (lane & 3) * 4;
    float sim[4];
    bool  val[4];
    float mx = -3.0e38f;
    #pragma unroll
    for (int m = 0; m < 4; m++) {
        const int   k    = kbase + m;
        const float invk = 1.0f / fmaxf(sqrtf(snorm[w][k]), 1e-12f);
        sim[m] = a[m] * inva * invk * 10.0f;
        val[m] = ((k >> 1) != i) || (k == 2 * i + 1);
        if (val[m]) mx = fmaxf(mx, sim[m]);
    }
    mx = fmaxf(mx, __shfl_xor_sync(FULL, mx, 1));
    mx = fmaxf(mx, __shfl_xor_sync(FULL, mx, 2));
    float sum = 0.f;
    #pragma unroll
    for (int m = 0; m < 4; m++)
        if (val[m]) sum += __expf(sim[m] - mx);
    sum += __shfl_xor_sync(FULL, sum, 1);
    sum += __shfl_xor_sync(FULL, sum, 2);

    float contrib = 0.f;
    #pragma unroll
    for (int m = 0; m < 4; m++)
        if (kbase + m == 2 * i + 1)                  // this sim is the positive
            contrib = (mx + __logf(sum)) - sim[m];
    #pragma unroll
    for (int off = 16; off > 0; off >>= 1)
        contrib += __shfl_xor_sync(FULL, contrib, off);
    if (lane == 0) g_partials[b] = contrib;

    // ---- deterministic fused finish (ticket; last CTA reduces) ----
    __syncthreads();
    if (tid == 0) {
        __threadfence();
        const unsigned tk = atomicAdd(&g_ticket, 1u);
        sFlag = (tk == gridDim.x - 1) ? 1u : 0u;
    }
    __syncthreads();
    if (sFlag) {
        float s = 0.f;
        #pragma unroll
        for (int m = 0; m < kB / 128; m++)
            s += __ldcg(&g_partials[tid + m * 128]);   // fixed order: deterministic
        #pragma unroll
        for (int off = 16; off > 0; off >>= 1)
            s += __shfl_xor_sync(FULL, s, off);
        if (lane == 0) sred[w] = s;
        __syncthreads();
        if (tid == 0) {
            out[0] = (sred[0] + sred[1] + sred[2] + sred[3]) * (1.0f / (8.0f * 4096.0f));
            g_ticket = 0u;   // reset for next graph replay
        }
    }
}

extern "C" void kernel_launch(void* const* d_in, const int* in_sizes, int n_in,
                              void* d_out, int out_size) {
    (void)in_sizes; (void)n_in; (void)out_size;
    const float* inp = (const float*)d_in[0];
    ntxent_warp<<<kB / 4, 128>>>(inp, (float*)d_out);
}